// round 1
// baseline (speedup 1.0000x reference)
#include <cuda_runtime.h>
#include <cstdint>

#define N_NODES 100000
#define F 64

// Scratch accumulator (allocation-free rule: __device__ global)
__device__ float g_support[N_NODES * F];

// ---------------------------------------------------------------------------
// Kernel 0: zero the scratch accumulator
// ---------------------------------------------------------------------------
__global__ void zero_support_kernel() {
    const int n4 = N_NODES * F / 4;
    float4* p = reinterpret_cast<float4*>(g_support);
    const float4 z = make_float4(0.f, 0.f, 0.f, 0.f);
    for (int i = blockIdx.x * blockDim.x + threadIdx.x; i < n4;
         i += gridDim.x * blockDim.x) {
        p[i] = z;
    }
}

// ---------------------------------------------------------------------------
// Kernel 1: edge scatter.  One warp per edge; each lane handles 2 features
// via a single red.global.add.v2.f32 (vector reduction, sm_90+).
// x and support both fit in L2, so gathers + atomics are L2-resident.
// ---------------------------------------------------------------------------
__global__ void scatter_edges_kernel(const float* __restrict__ x,
                                     const int*   __restrict__ edge_row,
                                     const int*   __restrict__ edge_col,
                                     const float* __restrict__ edge_val,
                                     int n_edges) {
    const int lane   = threadIdx.x & 31;
    const int warp   = (blockIdx.x * blockDim.x + threadIdx.x) >> 5;
    const int nwarps = (gridDim.x * blockDim.x) >> 5;

    for (int e = warp; e < n_edges; e += nwarps) {
        const int   r = edge_row[e];
        const int   c = edge_col[e];
        const float v = edge_val[e];

        const float2* xp = reinterpret_cast<const float2*>(x + (size_t)c * F);
        float2 m = xp[lane];
        m.x *= v;
        m.y *= v;

        float* dst = g_support + (size_t)r * F + lane * 2;
        asm volatile("red.global.add.v2.f32 [%0], {%1, %2};"
                     :: "l"(dst), "f"(m.x), "f"(m.y)
                     : "memory");
    }
}

// ---------------------------------------------------------------------------
// Kernel 2: out = normalize_rows(support @ W + b)
// One warp per node row. W cached in shared memory.
// Lane L holds support[2L], support[2L+1]; broadcasts via shfl.
// Lane L produces out columns L and L+32.
// ---------------------------------------------------------------------------
__global__ void gemm_norm_kernel(const float* __restrict__ weight,  // [in_f=64, out_f=64]
                                 const float* __restrict__ bias,    // [64]
                                 float* __restrict__ out) {
    __shared__ float sW[F][F + 1];
    __shared__ float sb[F];

    for (int i = threadIdx.x; i < F * F; i += blockDim.x)
        sW[i / F][i % F] = weight[i];
    if (threadIdx.x < F) sb[threadIdx.x] = bias[threadIdx.x];
    __syncthreads();

    const int lane = threadIdx.x & 31;
    const int wib  = threadIdx.x >> 5;
    const int row  = blockIdx.x * (blockDim.x >> 5) + wib;
    if (row >= N_NODES) return;

    const float2* sp = reinterpret_cast<const float2*>(g_support + (size_t)row * F);
    const float2 s = sp[lane];          // s[2*lane], s[2*lane+1]

    float acc0 = sb[lane];
    float acc1 = sb[lane + 32];

#pragma unroll
    for (int k = 0; k < 32; k++) {
        const float sk0 = __shfl_sync(0xffffffffu, s.x, k);   // support[2k]
        const float sk1 = __shfl_sync(0xffffffffu, s.y, k);   // support[2k+1]
        acc0 += sk0 * sW[2 * k][lane]      + sk1 * sW[2 * k + 1][lane];
        acc1 += sk0 * sW[2 * k][lane + 32] + sk1 * sW[2 * k + 1][lane + 32];
    }

    // row L2 norm over 64 outputs (warp-wide reduce of both halves)
    float sq = acc0 * acc0 + acc1 * acc1;
#pragma unroll
    for (int off = 16; off > 0; off >>= 1)
        sq += __shfl_xor_sync(0xffffffffu, sq, off);

    const float inv = rsqrtf(sq);

    out[(size_t)row * F + lane]      = acc0 * inv;
    out[(size_t)row * F + lane + 32] = acc1 * inv;
}

// ---------------------------------------------------------------------------
// Launch
// inputs (metadata order): x, edge_row, edge_col, edge_val, weight, bias
// ---------------------------------------------------------------------------
extern "C" void kernel_launch(void* const* d_in, const int* in_sizes, int n_in,
                              void* d_out, int out_size) {
    const float* x        = (const float*)d_in[0];
    const int*   edge_row = (const int*)  d_in[1];
    const int*   edge_col = (const int*)  d_in[2];
    const float* edge_val = (const float*)d_in[3];
    const float* weight   = (const float*)d_in[4];
    const float* bias     = (const float*)d_in[5];
    float*       out      = (float*)d_out;

    const int n_edges = in_sizes[1];

    // Kernel 0: zero scratch
    zero_support_kernel<<<1184, 256>>>();

    // Kernel 1: scatter (grid sized for full occupancy: 8 blocks/SM on ~148 SMs)
    scatter_edges_kernel<<<1184, 256>>>(x, edge_row, edge_col, edge_val, n_edges);

    // Kernel 2: GEMM + bias + L2 normalize. 8 rows (warps) per block.
    const int rows_per_block = 256 / 32;
    const int nblocks = (N_NODES + rows_per_block - 1) / rows_per_block;
    gemm_norm_kernel<<<nblocks, 256>>>(weight, bias, out);
}

// round 2
// speedup vs baseline: 1.0850x; 1.0850x over previous
#include <cuda_runtime.h>
#include <cstdint>

#define N_NODES 100000
#define F 64

// Scratch accumulator (allocation-free rule: __device__ global)
__device__ float g_support[N_NODES * F];

// ---------------------------------------------------------------------------
// Kernel 0: zero the scratch accumulator
// ---------------------------------------------------------------------------
__global__ void zero_support_kernel() {
    const int n4 = N_NODES * F / 4;
    float4* p = reinterpret_cast<float4*>(g_support);
    const float4 z = make_float4(0.f, 0.f, 0.f, 0.f);
    for (int i = blockIdx.x * blockDim.x + threadIdx.x; i < n4;
         i += gridDim.x * blockDim.x) {
        p[i] = z;
    }
}

// ---------------------------------------------------------------------------
// Kernel 1: edge scatter.  Two edges per warp (16 lanes each); each lane
// handles 4 features via one red.global.add.v4.f32 (sm_90+ vector red).
// Halves red-op count and LDG count vs the v2/one-edge-per-warp version.
// x and support both fit in L2, so gathers + atomics are L2-resident.
// ---------------------------------------------------------------------------
__global__ void scatter_edges_kernel(const float* __restrict__ x,
                                     const int*   __restrict__ edge_row,
                                     const int*   __restrict__ edge_col,
                                     const float* __restrict__ edge_val,
                                     int n_edges) {
    const int lane = threadIdx.x & 31;
    const int half = lane >> 4;          // which edge within the warp (0/1)
    const int l16  = lane & 15;          // feature-chunk index (16 x float4)
    const int warp   = (blockIdx.x * blockDim.x + threadIdx.x) >> 5;
    const int nwarps = (gridDim.x * blockDim.x) >> 5;

    for (int base = warp * 2; base < n_edges; base += nwarps * 2) {
        const int e = base + half;
        if (e < n_edges) {
            const int   r = edge_row[e];
            const int   c = edge_col[e];
            const float v = edge_val[e];

            const float4* xp = reinterpret_cast<const float4*>(x + (size_t)c * F);
            float4 m = xp[l16];
            m.x *= v; m.y *= v; m.z *= v; m.w *= v;

            float* dst = g_support + (size_t)r * F + l16 * 4;
            asm volatile("red.global.add.v4.f32 [%0], {%1, %2, %3, %4};"
                         :: "l"(dst), "f"(m.x), "f"(m.y), "f"(m.z), "f"(m.w)
                         : "memory");
        }
    }
}

// ---------------------------------------------------------------------------
// Kernel 2: out = normalize_rows(support @ W + b)
// One warp per node row. W cached in shared memory.
// ---------------------------------------------------------------------------
__global__ void gemm_norm_kernel(const float* __restrict__ weight,  // [64,64]
                                 const float* __restrict__ bias,    // [64]
                                 float* __restrict__ out) {
    __shared__ float sW[F][F + 1];
    __shared__ float sb[F];

    for (int i = threadIdx.x; i < F * F; i += blockDim.x)
        sW[i / F][i % F] = weight[i];
    if (threadIdx.x < F) sb[threadIdx.x] = bias[threadIdx.x];
    __syncthreads();

    const int lane = threadIdx.x & 31;
    const int wib  = threadIdx.x >> 5;
    const int row  = blockIdx.x * (blockDim.x >> 5) + wib;
    if (row >= N_NODES) return;

    const float2* sp = reinterpret_cast<const float2*>(g_support + (size_t)row * F);
    const float2 s = sp[lane];          // s[2*lane], s[2*lane+1]

    float acc0 = sb[lane];
    float acc1 = sb[lane + 32];

#pragma unroll
    for (int k = 0; k < 32; k++) {
        const float sk0 = __shfl_sync(0xffffffffu, s.x, k);   // support[2k]
        const float sk1 = __shfl_sync(0xffffffffu, s.y, k);   // support[2k+1]
        acc0 += sk0 * sW[2 * k][lane]      + sk1 * sW[2 * k + 1][lane];
        acc1 += sk0 * sW[2 * k][lane + 32] + sk1 * sW[2 * k + 1][lane + 32];
    }

    float sq = acc0 * acc0 + acc1 * acc1;
#pragma unroll
    for (int off = 16; off > 0; off >>= 1)
        sq += __shfl_xor_sync(0xffffffffu, sq, off);

    const float inv = rsqrtf(sq);

    out[(size_t)row * F + lane]      = acc0 * inv;
    out[(size_t)row * F + lane + 32] = acc1 * inv;
}

// ---------------------------------------------------------------------------
// Launch
// inputs (metadata order): x, edge_row, edge_col, edge_val, weight, bias
// ---------------------------------------------------------------------------
extern "C" void kernel_launch(void* const* d_in, const int* in_sizes, int n_in,
                              void* d_out, int out_size) {
    const float* x        = (const float*)d_in[0];
    const int*   edge_row = (const int*)  d_in[1];
    const int*   edge_col = (const int*)  d_in[2];
    const float* edge_val = (const float*)d_in[3];
    const float* weight   = (const float*)d_in[4];
    const float* bias     = (const float*)d_in[5];
    float*       out      = (float*)d_out;

    const int n_edges = in_sizes[1];

    zero_support_kernel<<<1184, 256>>>();

    scatter_edges_kernel<<<1184, 256>>>(x, edge_row, edge_col, edge_val, n_edges);

    const int rows_per_block = 256 / 32;
    const int nblocks = (N_NODES + rows_per_block - 1) / rows_per_block;
    gemm_norm_kernel<<<nblocks, 256>>>(weight, bias, out);
}

// round 4
// speedup vs baseline: 1.1844x; 1.0916x over previous
#include <cuda_runtime.h>
#include <cstdint>

#define N_NODES 100000
#define F 64
#define E_MAX 2000000
#define SCAN_BLK 1024
#define NSCAN ((N_NODES + SCAN_BLK - 1) / SCAN_BLK)   // 98

// ---- scratch (allocation-free rule: __device__ globals) ----
__device__ int   g_deg[N_NODES];
__device__ int   g_off[N_NODES + 1];
__device__ int   g_cursor[N_NODES];
__device__ int   g_bsum[128];                     // padded >= NSCAN
__device__ int2  g_es[E_MAX];                     // bucketed (col, val_bits), 16 MB

// ---------------------------------------------------------------------------
// 1. zero degree counters
// ---------------------------------------------------------------------------
__global__ void zero_deg_kernel() {
    for (int i = blockIdx.x * blockDim.x + threadIdx.x; i < N_NODES;
         i += gridDim.x * blockDim.x)
        g_deg[i] = 0;
}

// ---------------------------------------------------------------------------
// 2. histogram of edge_row
// ---------------------------------------------------------------------------
__global__ void hist_kernel(const int* __restrict__ edge_row, int n_edges) {
    for (int e = blockIdx.x * blockDim.x + threadIdx.x; e < n_edges;
         e += gridDim.x * blockDim.x)
        atomicAdd(&g_deg[edge_row[e]], 1);
}

// ---------------------------------------------------------------------------
// 3a. per-block exclusive scan of degrees; block totals to g_bsum
// ---------------------------------------------------------------------------
__global__ void scan_local_kernel() {
    __shared__ int warp_sums[32];
    const int i    = blockIdx.x * SCAN_BLK + threadIdx.x;
    const int lane = threadIdx.x & 31;
    const int wid  = threadIdx.x >> 5;

    int v = (i < N_NODES) ? g_deg[i] : 0;
    int s = v;
#pragma unroll
    for (int o = 1; o < 32; o <<= 1) {
        int t = __shfl_up_sync(0xffffffffu, s, o);
        if (lane >= o) s += t;
    }
    if (lane == 31) warp_sums[wid] = s;
    __syncthreads();
    if (wid == 0) {
        int ws = warp_sums[lane];
#pragma unroll
        for (int o = 1; o < 32; o <<= 1) {
            int t = __shfl_up_sync(0xffffffffu, ws, o);
            if (lane >= o) ws += t;
        }
        warp_sums[lane] = ws;
    }
    __syncthreads();
    const int incl = s + (wid > 0 ? warp_sums[wid - 1] : 0);
    if (i < N_NODES) g_off[i] = incl - v;                 // block-local exclusive
    if (threadIdx.x == SCAN_BLK - 1) g_bsum[blockIdx.x] = warp_sums[31];
}

// ---------------------------------------------------------------------------
// 3b. exclusive scan of block sums (single block, 128 threads)
// ---------------------------------------------------------------------------
__global__ void scan_bsums_kernel() {
    __shared__ int ws[4];
    const int lane = threadIdx.x & 31;
    const int wid  = threadIdx.x >> 5;
    int v = (threadIdx.x < NSCAN) ? g_bsum[threadIdx.x] : 0;
    int s = v;
#pragma unroll
    for (int o = 1; o < 32; o <<= 1) {
        int t = __shfl_up_sync(0xffffffffu, s, o);
        if (lane >= o) s += t;
    }
    if (lane == 31) ws[wid] = s;
    __syncthreads();
    if (threadIdx.x == 0) {
        int run = 0;
#pragma unroll
        for (int w = 0; w < 4; w++) { int t = ws[w]; ws[w] = run; run += t; }
        g_off[N_NODES] = run;                              // == n_edges
    }
    __syncthreads();
    const int incl = s + ws[wid];
    if (threadIdx.x < NSCAN) g_bsum[threadIdx.x] = incl - v;  // exclusive
}

// ---------------------------------------------------------------------------
// 3c. add block offsets; init cursors
// ---------------------------------------------------------------------------
__global__ void scan_add_kernel() {
    const int i = blockIdx.x * SCAN_BLK + threadIdx.x;
    if (i < N_NODES) {
        const int o = g_off[i] + g_bsum[blockIdx.x];
        g_off[i]    = o;
        g_cursor[i] = o;
    }
}

// ---------------------------------------------------------------------------
// 4. bucket edges by row
// ---------------------------------------------------------------------------
__global__ void bucket_kernel(const int*   __restrict__ edge_row,
                              const int*   __restrict__ edge_col,
                              const float* __restrict__ edge_val,
                              int n_edges) {
    for (int e = blockIdx.x * blockDim.x + threadIdx.x; e < n_edges;
         e += gridDim.x * blockDim.x) {
        const int r = edge_row[e];
        const int p = atomicAdd(&g_cursor[r], 1);
        g_es[p] = make_int2(edge_col[e], __float_as_int(edge_val[e]));
    }
}

// ---------------------------------------------------------------------------
// 5. fused pull + GEMM + bias + L2 normalize.
// One warp per row: accumulate support row in registers (no atomics, no
// support round-trip), then 64x64 GEMM via shfl broadcast with W in smem,
// warp-reduce the squared norm, write normalized output.
// ---------------------------------------------------------------------------
__global__ void pull_gemm_norm_kernel(const float* __restrict__ x,
                                      const float* __restrict__ weight,
                                      const float* __restrict__ bias,
                                      float* __restrict__ out) {
    __shared__ float sW[F][F + 1];
    __shared__ float sb[F];

    for (int i = threadIdx.x; i < F * F; i += blockDim.x)
        sW[i / F][i % F] = weight[i];
    if (threadIdx.x < F) sb[threadIdx.x] = bias[threadIdx.x];
    __syncthreads();

    const int lane = threadIdx.x & 31;
    const int row  = blockIdx.x * (blockDim.x >> 5) + (threadIdx.x >> 5);
    if (row >= N_NODES) return;

    const int beg = g_off[row];
    const int end = g_off[row + 1];

    // ---- pull: lane holds support[2*lane], support[2*lane+1] ----
    float2 acc = make_float2(0.f, 0.f);
    int e = beg;
    for (; e + 4 <= end; e += 4) {                 // x4 unroll for gather MLP
        const int2 c0 = g_es[e + 0];
        const int2 c1 = g_es[e + 1];
        const int2 c2 = g_es[e + 2];
        const int2 c3 = g_es[e + 3];
        const float2 x0 = reinterpret_cast<const float2*>(x + (size_t)c0.x * F)[lane];
        const float2 x1 = reinterpret_cast<const float2*>(x + (size_t)c1.x * F)[lane];
        const float2 x2 = reinterpret_cast<const float2*>(x + (size_t)c2.x * F)[lane];
        const float2 x3 = reinterpret_cast<const float2*>(x + (size_t)c3.x * F)[lane];
        const float v0 = __int_as_float(c0.y), v1 = __int_as_float(c1.y);
        const float v2 = __int_as_float(c2.y), v3 = __int_as_float(c3.y);
        acc.x += v0 * x0.x + v1 * x1.x + v2 * x2.x + v3 * x3.x;
        acc.y += v0 * x0.y + v1 * x1.y + v2 * x2.y + v3 * x3.y;
    }
    for (; e < end; e++) {
        const int2 c = g_es[e];
        const float2 xv = reinterpret_cast<const float2*>(x + (size_t)c.x * F)[lane];
        const float v = __int_as_float(c.y);
        acc.x += v * xv.x;
        acc.y += v * xv.y;
    }

    // ---- GEMM: out_row = support_row @ W + b ----
    float acc0 = sb[lane];
    float acc1 = sb[lane + 32];
#pragma unroll
    for (int k = 0; k < 32; k++) {
        const float sk0 = __shfl_sync(0xffffffffu, acc.x, k);   // support[2k]
        const float sk1 = __shfl_sync(0xffffffffu, acc.y, k);   // support[2k+1]
        acc0 += sk0 * sW[2 * k][lane]      + sk1 * sW[2 * k + 1][lane];
        acc1 += sk0 * sW[2 * k][lane + 32] + sk1 * sW[2 * k + 1][lane + 32];
    }

    // ---- row L2 normalize ----
    float sq = acc0 * acc0 + acc1 * acc1;
#pragma unroll
    for (int off = 16; off > 0; off >>= 1)
        sq += __shfl_xor_sync(0xffffffffu, sq, off);
    const float inv = rsqrtf(sq);

    out[(size_t)row * F + lane]      = acc0 * inv;
    out[(size_t)row * F + lane + 32] = acc1 * inv;
}

// ---------------------------------------------------------------------------
// Launch
// inputs: x, edge_row, edge_col, edge_val, weight, bias
// ---------------------------------------------------------------------------
extern "C" void kernel_launch(void* const* d_in, const int* in_sizes, int n_in,
                              void* d_out, int out_size) {
    const float* x        = (const float*)d_in[0];
    const int*   edge_row = (const int*)  d_in[1];
    const int*   edge_col = (const int*)  d_in[2];
    const float* edge_val = (const float*)d_in[3];
    const float* weight   = (const float*)d_in[4];
    const float* bias     = (const float*)d_in[5];
    float*       out      = (float*)d_out;

    const int n_edges = in_sizes[1];

    zero_deg_kernel<<<98, 1024>>>();
    hist_kernel<<<1184, 256>>>(edge_row, n_edges);
    scan_local_kernel<<<NSCAN, SCAN_BLK>>>();
    scan_bsums_kernel<<<1, 128>>>();
    scan_add_kernel<<<NSCAN, SCAN_BLK>>>();
    bucket_kernel<<<1184, 256>>>(edge_row, edge_col, edge_val, n_edges);

    const int rows_per_block = 256 / 32;
    const int nblocks = (N_NODES + rows_per_block - 1) / rows_per_block;
    pull_gemm_norm_kernel<<<nblocks, 256>>>(x, weight, bias, out);
}